// round 5
// baseline (speedup 1.0000x reference)
#include <cuda_runtime.h>
#include <cuda_fp16.h>
#include <math.h>

// ---------------- problem constants ----------------
#define N_ROWS 38912      // B*NPTS = 2048*19
#define NDIM   256
#define BOOK   2048
#define CBLK   16         // BOOK / 128 column blocks
#define TM     128
#define TN     128
#define PQ_IDX    9961472
#define LG_OFF    9961473
#define EPSF      1e-10f

// ---------------- device scratch (static; no runtime allocation) ----------------
__device__ __half g_Ph[(size_t)N_ROWS * BOOK];     // unnormalized exp(y - pm_blk), fp16
__device__ __half g_zeh[(size_t)N_ROWS * NDIM];    // ze hi fp16
__device__ __half g_zel[(size_t)N_ROWS * NDIM];    // ze lo fp16 (residual)
__device__ __half g_bookh[(size_t)BOOK * NDIM];    // book hi fp16
__device__ __half g_bookl[(size_t)BOOK * NDIM];    // book lo fp16 (residual)
__device__ float  g_zn[N_ROWS];                    // ||z||^2 (fp32 exact)
__device__ float  g_bn[BOOK];                      // ||e||^2 (fp32 exact)
__device__ float  g_pm[N_ROWS * CBLK];             // per-block row max of y
__device__ float  g_pl[N_ROWS * CBLK];             // per-block sum exp(y - pm)
__device__ float  g_sc[N_ROWS * CBLK];             // exp(pm - m)/l  per block

// ---------------- small helpers ----------------
__device__ __forceinline__ unsigned sptr(const void* p) {
    return (unsigned)__cvta_generic_to_shared(p);
}

__device__ __forceinline__ void ldsm4(unsigned addr, unsigned& r0, unsigned& r1,
                                      unsigned& r2, unsigned& r3) {
    asm volatile("ldmatrix.sync.aligned.m8n8.x4.shared.b16 {%0,%1,%2,%3}, [%4];"
                 : "=r"(r0), "=r"(r1), "=r"(r2), "=r"(r3) : "r"(addr));
}
__device__ __forceinline__ void ldsm4t(unsigned addr, unsigned& r0, unsigned& r1,
                                       unsigned& r2, unsigned& r3) {
    asm volatile("ldmatrix.sync.aligned.m8n8.x4.trans.shared.b16 {%0,%1,%2,%3}, [%4];"
                 : "=r"(r0), "=r"(r1), "=r"(r2), "=r"(r3) : "r"(addr));
}
__device__ __forceinline__ void mma16816(float* c, const unsigned* a,
                                         unsigned b0, unsigned b1) {
    asm volatile(
        "mma.sync.aligned.m16n8k16.row.col.f32.f16.f16.f32 "
        "{%0,%1,%2,%3}, {%4,%5,%6,%7}, {%8,%9}, {%0,%1,%2,%3};"
        : "+f"(c[0]), "+f"(c[1]), "+f"(c[2]), "+f"(c[3])
        : "r"(a[0]), "r"(a[1]), "r"(a[2]), "r"(a[3]), "r"(b0), "r"(b1));
}

// ---------------- K0: fp16 hi/lo split + squared norms ----------------
// which==0: book (2048 rows), which==1: ze (38912 rows)
__global__ void k_prep(const float* __restrict__ src, int which) {
    int r = blockIdx.x;
    int t = threadIdx.x;   // 256 threads = NDIM
    size_t idx = (size_t)r * NDIM + t;
    float v = src[idx];
    __half h = __float2half_rn(v);
    __half l = __float2half_rn(v - __half2float(h));
    if (which == 0) { g_bookh[idx] = h; g_bookl[idx] = l; }
    else            { g_zeh[idx]  = h; g_zel[idx]  = l; }
    float s = v * v;
    #pragma unroll
    for (int o = 16; o; o >>= 1) s += __shfl_xor_sync(0xffffffffu, s, o);
    __shared__ float red[8];
    if ((t & 31) == 0) red[t >> 5] = s;
    __syncthreads();
    if (t == 0) {
        float tot = 0.f;
        #pragma unroll
        for (int i = 0; i < 8; i++) tot += red[i];
        if (which == 0) g_bn[r] = tot; else g_zn[r] = tot;
    }
}

// write precision_q scalar
__global__ void k_scalar(const float* __restrict__ lpqP, float* __restrict__ out) {
    out[PQ_IDX] = 0.5f / fmaxf(expf(lpqP[0]), EPSF);
}

// ---------------- K1: split GEMM1 (S = Z @ Book^T) + logits + gumbel + partial softmax ----------------
__global__ __launch_bounds__(256) void k_gemm1(const float* __restrict__ U,
                                               const float* __restrict__ tempP,
                                               const float* __restrict__ lpqP,
                                               float* __restrict__ out) {
    const int ct = blockIdx.x;          // col tile 0..15
    const int rt = blockIdx.y;          // row tile 0..303
    const int rowBase = rt * TM;
    const int colBase = ct * TN;

    __shared__ __half Ah[TM * 40];
    __shared__ __half Al[TM * 40];
    __shared__ __half Bh[TN * 40];
    __shared__ __half Bl[TN * 40];
    __shared__ float pm_s[TM];
    __shared__ float pl_s[TM];

    const int t = threadIdx.x;
    const int lane = t & 31, warp = t >> 5;
    const int wr = warp >> 1;           // 0..3 : 32-row group
    const int wc = warp & 1;            // 0..1 : 64-col half

    float acc[2][8][4];
    #pragma unroll
    for (int i = 0; i < 2; i++)
        #pragma unroll
        for (int j = 0; j < 8; j++)
            #pragma unroll
            for (int c = 0; c < 4; c++) acc[i][j][c] = 0.f;

    const unsigned ahB = sptr(Ah), alB = sptr(Al);
    const unsigned bhB = sptr(Bh), blB = sptr(Bl);

    for (int kc = 0; kc < NDIM; kc += 32) {
        __syncthreads();
        #pragma unroll
        for (int i = 0; i < 2; i++) {
            int id = t + 256 * i;
            int r = id >> 2, c = id & 3;
            size_t oa = (size_t)(rowBase + r) * NDIM + kc + c * 8;
            *(uint4*)(&Ah[r * 40 + c * 8]) = *(const uint4*)(&g_zeh[oa]);
            *(uint4*)(&Al[r * 40 + c * 8]) = *(const uint4*)(&g_zel[oa]);
            size_t ob = (size_t)(colBase + r) * NDIM + kc + c * 8;
            *(uint4*)(&Bh[r * 40 + c * 8]) = *(const uint4*)(&g_bookh[ob]);
            *(uint4*)(&Bl[r * 40 + c * 8]) = *(const uint4*)(&g_bookl[ob]);
        }
        __syncthreads();
        #pragma unroll
        for (int s = 0; s < 2; s++) {
            const int kb = s * 16;
            const unsigned aoff = ((wr * 32 + (lane & 15)) * 40 + kb + (lane >> 4) * 8) * 2;
            unsigned aH[2][4], aL[2][4], bH[4][4], bL[4][4];
            #pragma unroll
            for (int i = 0; i < 2; i++)
                ldsm4(ahB + aoff + i * 16 * 40 * 2, aH[i][0], aH[i][1], aH[i][2], aH[i][3]);
            #pragma unroll
            for (int jj = 0; jj < 4; jj++) {
                unsigned boff = ((wc * 64 + jj * 16 + (lane & 7) + (lane >> 4) * 8) * 40
                                 + kb + ((lane >> 3) & 1) * 8) * 2;
                ldsm4(bhB + boff, bH[jj][0], bH[jj][1], bH[jj][2], bH[jj][3]);
            }
            #pragma unroll
            for (int i = 0; i < 2; i++)
                #pragma unroll
                for (int j = 0; j < 8; j++)
                    mma16816(acc[i][j], aH[i], bH[j >> 1][(j & 1) * 2], bH[j >> 1][(j & 1) * 2 + 1]);
            #pragma unroll
            for (int jj = 0; jj < 4; jj++) {
                unsigned boff = ((wc * 64 + jj * 16 + (lane & 7) + (lane >> 4) * 8) * 40
                                 + kb + ((lane >> 3) & 1) * 8) * 2;
                ldsm4(blB + boff, bL[jj][0], bL[jj][1], bL[jj][2], bL[jj][3]);
            }
            #pragma unroll
            for (int i = 0; i < 2; i++)
                #pragma unroll
                for (int j = 0; j < 8; j++)
                    mma16816(acc[i][j], aH[i], bL[j >> 1][(j & 1) * 2], bL[j >> 1][(j & 1) * 2 + 1]);
            #pragma unroll
            for (int i = 0; i < 2; i++)
                ldsm4(alB + aoff + i * 16 * 40 * 2, aL[i][0], aL[i][1], aL[i][2], aL[i][3]);
            #pragma unroll
            for (int i = 0; i < 2; i++)
                #pragma unroll
                for (int j = 0; j < 8; j++)
                    mma16816(acc[i][j], aL[i], bH[j >> 1][(j & 1) * 2], bH[j >> 1][(j & 1) * 2 + 1]);
        }
    }

    // ---------------- epilogue ----------------
    const float pq   = 0.5f / fmaxf(expf(lpqP[0]), EPSF);
    const float invT = 1.0f / tempP[0];
    float* __restrict__ outLg = out + LG_OFF;

    float rmax[2][2] = {{-INFINITY, -INFINITY}, {-INFINITY, -INFINITY}};

    // pass 1: logits -> gmem, y = (logits+g)/T kept in acc, track row max
    #pragma unroll
    for (int i = 0; i < 2; i++) {
        #pragma unroll
        for (int c = 0; c < 4; c++) {
            const int h  = c >> 1;
            const int rl = wr * 32 + i * 16 + (lane >> 2) + h * 8;
            const int grow = rowBase + rl;
            const float zn = g_zn[grow];
            #pragma unroll
            for (int j = 0; j < 8; j++) {
                const int cl = wc * 64 + j * 8 + (lane & 3) * 2 + (c & 1);
                const int gcol = colBase + cl;
                float d = acc[i][j][c];
                float lg = (2.f * d - zn - g_bn[gcol]) * pq;
                outLg[(size_t)grow * BOOK + gcol] = lg;
                float u = U[(size_t)grow * BOOK + gcol];
                // accurate inner log (near-1 u -> row-max gumbels), fast outer log
                float w = -logf(u + EPSF) + EPSF;
                float g = -__logf(w);
                float y = (lg + g) * invT;
                acc[i][j][c] = y;
                rmax[i][h] = fmaxf(rmax[i][h], y);
            }
        }
    }
    // quad reduce (lanes sharing rows differ only in lane&3)
    #pragma unroll
    for (int i = 0; i < 2; i++)
        #pragma unroll
        for (int h = 0; h < 2; h++) {
            float m = rmax[i][h];
            m = fmaxf(m, __shfl_xor_sync(0xffffffffu, m, 1));
            m = fmaxf(m, __shfl_xor_sync(0xffffffffu, m, 2));
            rmax[i][h] = m;
        }
    if (wc == 0 && (lane & 3) == 0) {
        #pragma unroll
        for (int i = 0; i < 2; i++)
            #pragma unroll
            for (int h = 0; h < 2; h++)
                pm_s[wr * 32 + i * 16 + (lane >> 2) + h * 8] = rmax[i][h];
    }
    __syncthreads();
    if (wc == 1 && (lane & 3) == 0) {
        #pragma unroll
        for (int i = 0; i < 2; i++)
            #pragma unroll
            for (int h = 0; h < 2; h++) {
                int idx = wr * 32 + i * 16 + (lane >> 2) + h * 8;
                pm_s[idx] = fmaxf(pm_s[idx], rmax[i][h]);
            }
    }
    __syncthreads();

    // pass 2: P = exp(y - pm), store fp16, accumulate partial sums of the
    // QUANTIZED value (common-mode quantization error cancels in normalization)
    float psum[2][2] = {{0.f, 0.f}, {0.f, 0.f}};
    #pragma unroll
    for (int i = 0; i < 2; i++) {
        #pragma unroll
        for (int c = 0; c < 4; c++) {
            const int h  = c >> 1;
            const int rl = wr * 32 + i * 16 + (lane >> 2) + h * 8;
            const int grow = rowBase + rl;
            const float pm = pm_s[rl];
            #pragma unroll
            for (int j = 0; j < 8; j++) {
                const int cl = wc * 64 + j * 8 + (lane & 3) * 2 + (c & 1);
                const int gcol = colBase + cl;
                float P = __expf(acc[i][j][c] - pm);
                __half ph = __float2half_rn(P);
                psum[i][h] += __half2float(ph);
                g_Ph[(size_t)grow * BOOK + gcol] = ph;
            }
        }
    }
    #pragma unroll
    for (int i = 0; i < 2; i++)
        #pragma unroll
        for (int h = 0; h < 2; h++) {
            float s = psum[i][h];
            s += __shfl_xor_sync(0xffffffffu, s, 1);
            s += __shfl_xor_sync(0xffffffffu, s, 2);
            psum[i][h] = s;
        }
    if (wc == 0 && (lane & 3) == 0) {
        #pragma unroll
        for (int i = 0; i < 2; i++)
            #pragma unroll
            for (int h = 0; h < 2; h++)
                pl_s[wr * 32 + i * 16 + (lane >> 2) + h * 8] = psum[i][h];
    }
    __syncthreads();
    if (wc == 1 && (lane & 3) == 0) {
        #pragma unroll
        for (int i = 0; i < 2; i++)
            #pragma unroll
            for (int h = 0; h < 2; h++) {
                int idx = wr * 32 + i * 16 + (lane >> 2) + h * 8;
                pl_s[idx] += psum[i][h];
            }
    }
    __syncthreads();
    if (t < TM) {
        g_pm[(size_t)(rowBase + t) * CBLK + ct] = pm_s[t];
        g_pl[(size_t)(rowBase + t) * CBLK + ct] = pl_s[t];
    }
}

// ---------------- K2: combine partial stats -> per-block scale ----------------
__global__ void k_reduce() {
    int r = blockIdx.x * blockDim.x + threadIdx.x;
    if (r >= N_ROWS) return;
    float m = -INFINITY;
    #pragma unroll
    for (int cb = 0; cb < CBLK; cb++) m = fmaxf(m, g_pm[(size_t)r * CBLK + cb]);
    float l = 0.f;
    #pragma unroll
    for (int cb = 0; cb < CBLK; cb++)
        l += g_pl[(size_t)r * CBLK + cb] * __expf(g_pm[(size_t)r * CBLK + cb] - m);
    float inv = 1.f / l;
    #pragma unroll
    for (int cb = 0; cb < CBLK; cb++)
        g_sc[(size_t)r * CBLK + cb] = __expf(g_pm[(size_t)r * CBLK + cb] - m) * inv;
}

// ---------------- K3: split GEMM2 (zq = enc @ Book) ----------------
__global__ __launch_bounds__(256) void k_gemm2(float* __restrict__ out) {
    const int dt = blockIdx.x;          // dim tile 0..1
    const int rt = blockIdx.y;          // row tile 0..303
    const int rowBase = rt * TM;
    const int dimBase = dt * 128;

    __shared__ __half As[TM * 40];      // scaled P' tile [row][k]
    __shared__ __half Bsh[32 * 136];    // book hi chunk [k][n]
    __shared__ __half Bsl[32 * 136];    // book lo chunk [k][n]

    const int t = threadIdx.x;
    const int lane = t & 31, warp = t >> 5;
    const int wr = warp >> 1, wc = warp & 1;

    float acc[2][8][4];
    #pragma unroll
    for (int i = 0; i < 2; i++)
        #pragma unroll
        for (int j = 0; j < 8; j++)
            #pragma unroll
            for (int c = 0; c < 4; c++) acc[i][j][c] = 0.f;

    const unsigned aBase = sptr(As);
    const unsigned bhB = sptr(Bsh);
    const unsigned blB = sptr(Bsl);

    for (int kc = 0; kc < BOOK; kc += 32) {
        __syncthreads();
        #pragma unroll
        for (int i = 0; i < 2; i++) {
            int id = t + 256 * i;
            { // A: P' scaled by per-(row, 128-block) scale
                int r = id >> 2, c = id & 3;
                uint4 v = *(const uint4*)(&g_Ph[(size_t)(rowBase + r) * BOOK + kc + c * 8]);
                float s = g_sc[(size_t)(rowBase + r) * CBLK + (kc >> 7)];
                __half2 hs = __float2half2_rn(s);
                __half2* hv = (__half2*)&v;
                hv[0] = __hmul2(hv[0], hs); hv[1] = __hmul2(hv[1], hs);
                hv[2] = __hmul2(hv[2], hs); hv[3] = __hmul2(hv[3], hs);
                *(uint4*)(&As[r * 40 + c * 8]) = v;
            }
            { // B: book rows kc..kc+31, dims dimBase..dimBase+127, hi and lo
                int r = id >> 4, c = id & 15;
                size_t ob = (size_t)(kc + r) * NDIM + dimBase + c * 8;
                *(uint4*)(&Bsh[r * 136 + c * 8]) = *(const uint4*)(&g_bookh[ob]);
                *(uint4*)(&Bsl[r * 136 + c * 8]) = *(const uint4*)(&g_bookl[ob]);
            }
        }
        __syncthreads();
        #pragma unroll
        for (int s = 0; s < 2; s++) {
            const int kb = s * 16;
            unsigned a[2][4];
            #pragma unroll
            for (int i = 0; i < 2; i++) {
                unsigned ad = aBase + ((wr * 32 + i * 16 + (lane & 15)) * 40
                                       + kb + (lane >> 4) * 8) * 2;
                ldsm4(ad, a[i][0], a[i][1], a[i][2], a[i][3]);
            }
            unsigned bH[4][4], bL[4][4];
            #pragma unroll
            for (int jj = 0; jj < 4; jj++) {
                unsigned boff = ((kb + (lane & 7) + ((lane >> 3) & 1) * 8) * 136
                                 + wc * 64 + jj * 16 + (lane >> 4) * 8) * 2;
                ldsm4t(bhB + boff, bH[jj][0], bH[jj][1], bH[jj][2], bH[jj][3]);
                ldsm4t(blB + boff, bL[jj][0], bL[jj][1], bL[jj][2], bL[jj][3]);
            }
            #pragma unroll
            for (int i = 0; i < 2; i++)
                #pragma unroll
                for (int j = 0; j < 8; j++) {
                    mma16816(acc[i][j], a[i], bH[j >> 1][(j & 1) * 2], bH[j >> 1][(j & 1) * 2 + 1]);
                    mma16816(acc[i][j], a[i], bL[j >> 1][(j & 1) * 2], bL[j >> 1][(j & 1) * 2 + 1]);
                }
        }
    }

    // epilogue: acc is already normalized zq
    #pragma unroll
    for (int i = 0; i < 2; i++)
        #pragma unroll
        for (int c = 0; c < 4; c++) {
            const int rl = wr * 32 + i * 16 + (lane >> 2) + (c >> 1) * 8;
            const int grow = rowBase + rl;
            #pragma unroll
            for (int j = 0; j < 8; j++) {
                const int cl = wc * 64 + j * 8 + (lane & 3) * 2 + (c & 1);
                out[(size_t)grow * NDIM + dimBase + cl] = acc[i][j][c];
            }
        }
}

// ---------------- launcher ----------------
extern "C" void kernel_launch(void* const* d_in, const int* in_sizes, int n_in,
                              void* d_out, int out_size) {
    const float* ze   = (const float*)d_in[0];
    const float* temp = (const float*)d_in[1];
    const float* U    = (const float*)d_in[2];
    const float* book = (const float*)d_in[3];
    const float* lpq  = (const float*)d_in[4];
    float* out = (float*)d_out;

    k_prep<<<BOOK,   NDIM>>>(book, 0);
    k_prep<<<N_ROWS, NDIM>>>(ze, 1);
    k_scalar<<<1, 1>>>(lpq, out);
    k_gemm1<<<dim3(CBLK, N_ROWS / TM), 256>>>(U, temp, lpq, out);
    k_reduce<<<N_ROWS / 256, 256>>>();
    k_gemm2<<<dim3(NDIM / 128, N_ROWS / TM), 256>>>(out);
}

// round 10
// speedup vs baseline: 1.3701x; 1.3701x over previous
#include <cuda_runtime.h>
#include <cuda_fp16.h>
#include <math.h>

#define N_ROWS 38912
#define NDIM   256
#define BOOK   2048
#define CBLK   16
#define PQ_IDX 9961472
#define LG_OFF 9961473
#define EPSF   1e-10f

// ---------------- device scratch ----------------
__device__ __half g_Ph[(size_t)N_ROWS * BOOK];
__device__ __half g_zeh[(size_t)N_ROWS * NDIM];
__device__ __half g_zel[(size_t)N_ROWS * NDIM];
__device__ __half g_bookh[BOOK * NDIM];
__device__ __half g_bookl[BOOK * NDIM];
__device__ __half g_bth[NDIM * BOOK];   // book^T hi: [dim][book]
__device__ __half g_btl[NDIM * BOOK];   // book^T lo
__device__ float  g_zn[N_ROWS];
__device__ float  g_bn[BOOK];
__device__ float  g_pm[(size_t)N_ROWS * CBLK];
__device__ float  g_linv[N_ROWS];

// ---------------- helpers ----------------
__device__ __forceinline__ unsigned sptr(const void* p) {
    return (unsigned)__cvta_generic_to_shared(p);
}
__device__ __forceinline__ void ldsm4(unsigned addr, unsigned& r0, unsigned& r1,
                                      unsigned& r2, unsigned& r3) {
    asm volatile("ldmatrix.sync.aligned.m8n8.x4.shared.b16 {%0,%1,%2,%3}, [%4];"
                 : "=r"(r0), "=r"(r1), "=r"(r2), "=r"(r3) : "r"(addr));
}
__device__ __forceinline__ void mma16816(float* c, const unsigned* a,
                                         unsigned b0, unsigned b1) {
    asm volatile(
        "mma.sync.aligned.m16n8k16.row.col.f32.f16.f16.f32 "
        "{%0,%1,%2,%3}, {%4,%5,%6,%7}, {%8,%9}, {%0,%1,%2,%3};"
        : "+f"(c[0]), "+f"(c[1]), "+f"(c[2]), "+f"(c[3])
        : "r"(a[0]), "r"(a[1]), "r"(a[2]), "r"(a[3]), "r"(b0), "r"(b1));
}
__device__ __forceinline__ void cpa16(unsigned dst, const void* src) {
    asm volatile("cp.async.cg.shared.global [%0], [%1], 16;" :: "r"(dst), "l"(src) : "memory");
}
#define CP_COMMIT() asm volatile("cp.async.commit_group;" ::: "memory")
#define CP_WAIT(n)  asm volatile("cp.async.wait_group %0;" :: "n"(n) : "memory")

// ---------------- K0a: book prep (hi/lo + transpose + norms) ----------------
__global__ void k_prep_book(const float* __restrict__ book) {
    int r = blockIdx.x, t = threadIdx.x;   // 2048 x 256
    size_t idx = (size_t)r * NDIM + t;
    float v = book[idx];
    __half h = __float2half_rn(v);
    __half l = __float2half_rn(v - __half2float(h));
    g_bookh[idx] = h;  g_bookl[idx] = l;
    g_bth[(size_t)t * BOOK + r] = h;
    g_btl[(size_t)t * BOOK + r] = l;
    float s = v * v;
    #pragma unroll
    for (int o = 16; o; o >>= 1) s += __shfl_xor_sync(0xffffffffu, s, o);
    __shared__ float red[8];
    if ((t & 31) == 0) red[t >> 5] = s;
    __syncthreads();
    if (t == 0) {
        float tot = 0.f;
        #pragma unroll
        for (int i = 0; i < 8; i++) tot += red[i];
        g_bn[r] = tot;
    }
}

// ---------------- K0b: ze prep ----------------
__global__ void k_prep_ze(const float* __restrict__ ze) {
    int r = blockIdx.x, t = threadIdx.x;
    size_t idx = (size_t)r * NDIM + t;
    float v = ze[idx];
    __half h = __float2half_rn(v);
    g_zeh[idx] = h;
    g_zel[idx] = __float2half_rn(v - __half2float(h));
    float s = v * v;
    #pragma unroll
    for (int o = 16; o; o >>= 1) s += __shfl_xor_sync(0xffffffffu, s, o);
    __shared__ float red[8];
    if ((t & 31) == 0) red[t >> 5] = s;
    __syncthreads();
    if (t == 0) {
        float tot = 0.f;
        #pragma unroll
        for (int i = 0; i < 8; i++) tot += red[i];
        g_zn[r] = tot;
    }
}

__global__ void k_scalar(const float* __restrict__ lpqP, float* __restrict__ out) {
    out[PQ_IDX] = 0.5f / fmaxf(expf(lpqP[0]), EPSF);
}

// ---------------- K1: pipelined mma.sync GEMM1 (3 fused passes) + epilogue ----------------
// dynamic smem: 3 stages of (A 128x40h = 10240B, B 128x40h = 10240B), then pm_s, bn_s
#define G1_STAGE 20480
#define G1_SMEM  (3 * G1_STAGE + 1024)

__global__ void __launch_bounds__(256, 2) k_gemm1(
    const float* __restrict__ U, const float* __restrict__ tempP,
    const float* __restrict__ lpqP, float* __restrict__ out)
{
    extern __shared__ __align__(1024) char smem[];
    float* pm_s = (float*)(smem + 3 * G1_STAGE);
    float* bn_s = (float*)(smem + 3 * G1_STAGE + 512);
    const unsigned sb = sptr(smem);
    const int t = threadIdx.x, lane = t & 31, warp = t >> 5;
    const int ct = blockIdx.x, rt = blockIdx.y;
    const int rowBase = rt * 128, colBase = ct * 128;
    const int wr = warp >> 1, wc = warp & 1;

    if (t < 128) bn_s[t] = g_bn[colBase + t];

    float acc[2][8][4];
    #pragma unroll
    for (int i = 0; i < 2; i++)
        #pragma unroll
        for (int j = 0; j < 8; j++)
            #pragma unroll
            for (int c = 0; c < 4; c++) acc[i][j][c] = 0.f;

    // chunk c in [0,24): pass = c/8 -> (zh.bh, zh.bl, zl.bh); kc = (c&7)*32
    auto fill = [&](int c, int s) {
        const __half* Ag = (c < 16) ? g_zeh : g_zel;
        const __half* Bg = (c >= 8 && c < 16) ? g_bookl : g_bookh;
        const int kc = (c & 7) * 32;
        unsigned ab = sb + s * G1_STAGE;
        unsigned bb = ab + 10240;
        #pragma unroll
        for (int i = 0; i < 2; i++) {
            int id = t + 256 * i;
            int r = id >> 2, cc = id & 3;
            cpa16(ab + r * 80 + cc * 16, &Ag[(size_t)(rowBase + r) * NDIM + kc + cc * 8]);
            cpa16(bb + r * 80 + cc * 16, &Bg[(size_t)(colBase + r) * NDIM + kc + cc * 8]);
        }
        CP_COMMIT();
    };

    fill(0, 0); fill(1, 1); fill(2, 2);

    for (int it = 0; it < 24; it++) {
        const int s = it % 3;
        CP_WAIT(2);
        __syncthreads();
        const unsigned aB = sb + s * G1_STAGE;
        const unsigned bB = aB + 10240;
        #pragma unroll
        for (int sub = 0; sub < 2; sub++) {
            const int kb = sub * 16;
            unsigned a[2][4], b[4][4];
            #pragma unroll
            for (int i = 0; i < 2; i++)
                ldsm4(aB + ((wr * 32 + i * 16 + (lane & 15)) * 40 + kb + (lane >> 4) * 8) * 2,
                      a[i][0], a[i][1], a[i][2], a[i][3]);
            #pragma unroll
            for (int jj = 0; jj < 4; jj++)
                ldsm4(bB + ((wc * 64 + jj * 16 + (lane & 7) + (lane >> 4) * 8) * 40
                            + kb + ((lane >> 3) & 1) * 8) * 2,
                      b[jj][0], b[jj][1], b[jj][2], b[jj][3]);
            #pragma unroll
            for (int i = 0; i < 2; i++)
                #pragma unroll
                for (int j = 0; j < 8; j++)
                    mma16816(acc[i][j], a[i], b[j >> 1][(j & 1) * 2], b[j >> 1][(j & 1) * 2 + 1]);
        }
        __syncthreads();
        if (it + 3 < 24) fill(it + 3, s); else CP_COMMIT();
    }

    // ---------------- epilogue ----------------
    const float pq   = 0.5f / fmaxf(expf(lpqP[0]), EPSF);
    const float invT = 1.0f / tempP[0];
    float* __restrict__ outLg = out + LG_OFF;   // NOTE: odd float offset -> scalar stores only

    float rmax[2][2] = {{-INFINITY, -INFINITY}, {-INFINITY, -INFINITY}};

    // pass 1: logits -> gmem (scalar stores; base is 4B-aligned only), y kept in acc
    #pragma unroll
    for (int i = 0; i < 2; i++) {
        #pragma unroll
        for (int h = 0; h < 2; h++) {
            const int rl = wr * 32 + i * 16 + (lane >> 2) + h * 8;
            const int grow = rowBase + rl;
            const float zn = g_zn[grow];
            float* __restrict__ lgrow = outLg + (size_t)grow * BOOK + colBase;
            const float* __restrict__ urow = U + (size_t)grow * BOOK + colBase;
            #pragma unroll
            for (int j = 0; j < 8; j++) {
                const int cl = wc * 64 + j * 8 + (lane & 3) * 2;
                float d0 = acc[i][j][2 * h], d1 = acc[i][j][2 * h + 1];
                float lg0 = fmaf(2.f, d0, -(zn + bn_s[cl]))     * pq;
                float lg1 = fmaf(2.f, d1, -(zn + bn_s[cl + 1])) * pq;
                lgrow[cl]     = lg0;
                lgrow[cl + 1] = lg1;
                float2 u2 = *(const float2*)&urow[cl];
                float w0 = -logf(u2.x + EPSF) + EPSF;   // accurate inner log
                float w1 = -logf(u2.y + EPSF) + EPSF;
                float y0 = (lg0 - __logf(w0)) * invT;
                float y1 = (lg1 - __logf(w1)) * invT;
                acc[i][j][2 * h]     = y0;
                acc[i][j][2 * h + 1] = y1;
                rmax[i][h] = fmaxf(rmax[i][h], fmaxf(y0, y1));
            }
        }
    }
    // reduce row max within quad, then across the two col-half warps
    #pragma unroll
    for (int i = 0; i < 2; i++)
        #pragma unroll
        for (int h = 0; h < 2; h++) {
            float m = rmax[i][h];
            m = fmaxf(m, __shfl_xor_sync(0xffffffffu, m, 1));
            m = fmaxf(m, __shfl_xor_sync(0xffffffffu, m, 2));
            rmax[i][h] = m;
        }
    if (wc == 0 && (lane & 3) == 0) {
        #pragma unroll
        for (int i = 0; i < 2; i++)
            #pragma unroll
            for (int h = 0; h < 2; h++)
                pm_s[wr * 32 + i * 16 + (lane >> 2) + h * 8] = rmax[i][h];
    }
    __syncthreads();
    if (wc == 1 && (lane & 3) == 0) {
        #pragma unroll
        for (int i = 0; i < 2; i++)
            #pragma unroll
            for (int h = 0; h < 2; h++) {
                int idx = wr * 32 + i * 16 + (lane >> 2) + h * 8;
                pm_s[idx] = fmaxf(pm_s[idx], rmax[i][h]);
            }
    }
    __syncthreads();

    // pass 2: P' = exp(y - pm_tile) as half2 -> g_Ph (final sum done in k_reduce)
    #pragma unroll
    for (int i = 0; i < 2; i++) {
        #pragma unroll
        for (int h = 0; h < 2; h++) {
            const int rl = wr * 32 + i * 16 + (lane >> 2) + h * 8;
            const int grow = rowBase + rl;
            const float pm = pm_s[rl];
            __half* __restrict__ prow = g_Ph + (size_t)grow * BOOK + colBase;
            #pragma unroll
            for (int j = 0; j < 8; j++) {
                const int cl = wc * 64 + j * 8 + (lane & 3) * 2;
                __half2 p = __floats2half2_rn(__expf(acc[i][j][2 * h] - pm),
                                              __expf(acc[i][j][2 * h + 1] - pm));
                *(__half2*)&prow[cl] = p;
            }
        }
    }
    if (t < 128) g_pm[(size_t)(rowBase + t) * CBLK + ct] = pm_s[t];
}

// ---------------- K2: warp-per-row global rescale of P + 1/L ----------------
__global__ void k_reduce() {
    int gw = (blockIdx.x * blockDim.x + threadIdx.x) >> 5;
    int lane = threadIdx.x & 31;
    if (gw >= N_ROWS) return;
    size_t r = gw;
    float pm = (lane < CBLK) ? g_pm[r * CBLK + lane] : -INFINITY;
    float m = pm;
    #pragma unroll
    for (int o = 16; o; o >>= 1) m = fmaxf(m, __shfl_xor_sync(0xffffffffu, m, o));
    float sc = __expf(pm - m);           // valid for lanes 0..15 (one per 128-col block)
    uint4* row = (uint4*)(g_Ph + r * BOOK);
    float s = 0.f;
    #pragma unroll
    for (int v = 0; v < 8; v++) {
        uint4 q = row[v * 32 + lane];    // cols (v*32+lane)*8 .. +8
        float scb = __shfl_sync(0xffffffffu, sc, v * 2 + (lane >> 4));
        __half2 hs = __float2half2_rn(scb);
        __half2 h0 = __hmul2(*(__half2*)&q.x, hs);
        __half2 h1 = __hmul2(*(__half2*)&q.y, hs);
        __half2 h2 = __hmul2(*(__half2*)&q.z, hs);
        __half2 h3 = __hmul2(*(__half2*)&q.w, hs);
        float2 f0 = __half22float2(h0), f1 = __half22float2(h1);
        float2 f2 = __half22float2(h2), f3 = __half22float2(h3);
        s += (f0.x + f0.y) + (f1.x + f1.y) + (f2.x + f2.y) + (f3.x + f3.y);
        q.x = *(unsigned*)&h0; q.y = *(unsigned*)&h1;
        q.z = *(unsigned*)&h2; q.w = *(unsigned*)&h3;
        row[v * 32 + lane] = q;
    }
    #pragma unroll
    for (int o = 16; o; o >>= 1) s += __shfl_xor_sync(0xffffffffu, s, o);
    if (lane == 0) g_linv[r] = 1.f / s;
}

// ---------------- K3: pipelined mma.sync GEMM2 (zq = P@book hi+lo) ----------------
// dynamic smem: 3 stages of (A 10240B, Bh 10240B, Bl 10240B)
#define G2_STAGE 30720
#define G2_SMEM  (3 * G2_STAGE)

__global__ void __launch_bounds__(256, 2) k_gemm2(float* __restrict__ out) {
    extern __shared__ __align__(1024) char smem[];
    const unsigned sb = sptr(smem);
    const int t = threadIdx.x, lane = t & 31, warp = t >> 5;
    const int rowBase = blockIdx.y * 128, dimBase = blockIdx.x * 128;
    const int wr = warp >> 1, wc = warp & 1;

    float acc[2][8][4];
    #pragma unroll
    for (int i = 0; i < 2; i++)
        #pragma unroll
        for (int j = 0; j < 8; j++)
            #pragma unroll
            for (int c = 0; c < 4; c++) acc[i][j][c] = 0.f;

    auto fill = [&](int c, int s) {
        const int kc = c * 32;
        unsigned ab = sb + s * G2_STAGE;
        unsigned bhb = ab + 10240, blb = ab + 20480;
        #pragma unroll
        for (int i = 0; i < 2; i++) {
            int id = t + 256 * i;
            int r = id >> 2, cc = id & 3;
            cpa16(ab  + r * 80 + cc * 16, &g_Ph [(size_t)(rowBase + r) * BOOK + kc + cc * 8]);
            cpa16(bhb + r * 80 + cc * 16, &g_bth[(size_t)(dimBase + r) * BOOK + kc + cc * 8]);
            cpa16(blb + r * 80 + cc * 16, &g_btl[(size_t)(dimBase + r) * BOOK + kc + cc * 8]);
        }
        CP_COMMIT();
    };

    fill(0, 0); fill(1, 1); fill(2, 2);

    for (int it = 0; it < 64; it++) {
        const int s = it % 3;
        CP_WAIT(2);
        __syncthreads();
        const unsigned aB = sb + s * G2_STAGE;
        const unsigned bhB = aB + 10240, blB = aB + 20480;
        #pragma unroll
        for (int sub = 0; sub < 2; sub++) {
            const int kb = sub * 16;
            unsigned a[2][4], b[4][4];
            #pragma unroll
            for (int i = 0; i < 2; i++)
                ldsm4(aB + ((wr * 32 + i * 16 + (lane & 15)) * 40 + kb + (lane >> 4) * 8) * 2,
                      a[i][0], a[i][1], a[i][2], a[i][3]);
            #pragma unroll
            for (int jj = 0; jj < 4; jj++)
                ldsm4(bhB + ((wc * 64 + jj * 16 + (lane & 7) + (lane >> 4) * 8) * 40
                             + kb + ((lane >> 3) & 1) * 8) * 2,
                      b[jj][0], b[jj][1], b[jj][2], b[jj][3]);
            #pragma unroll
            for (int i = 0; i < 2; i++)
                #pragma unroll
                for (int j = 0; j < 8; j++)
                    mma16816(acc[i][j], a[i], b[j >> 1][(j & 1) * 2], b[j >> 1][(j & 1) * 2 + 1]);
            #pragma unroll
            for (int jj = 0; jj < 4; jj++)
                ldsm4(blB + ((wc * 64 + jj * 16 + (lane & 7) + (lane >> 4) * 8) * 40
                             + kb + ((lane >> 3) & 1) * 8) * 2,
                      b[jj][0], b[jj][1], b[jj][2], b[jj][3]);
            #pragma unroll
            for (int i = 0; i < 2; i++)
                #pragma unroll
                for (int j = 0; j < 8; j++)
                    mma16816(acc[i][j], a[i], b[j >> 1][(j & 1) * 2], b[j >> 1][(j & 1) * 2 + 1]);
        }
        __syncthreads();
        if (it + 3 < 64) fill(it + 3, s); else CP_COMMIT();
    }

    // epilogue: zq = acc * (1/L), float2 stores (even offsets; out base aligned)
    #pragma unroll
    for (int i = 0; i < 2; i++) {
        #pragma unroll
        for (int h = 0; h < 2; h++) {
            const int rl = wr * 32 + i * 16 + (lane >> 2) + h * 8;
            const int grow = rowBase + rl;
            const float linv = g_linv[grow];
            float* __restrict__ orow = out + (size_t)grow * NDIM + dimBase;
            #pragma unroll
            for (int j = 0; j < 8; j++) {
                const int cl = wc * 64 + j * 8 + (lane & 3) * 2;
                *(float2*)&orow[cl] = make_float2(acc[i][j][2 * h] * linv,
                                                  acc[i][j][2 * h + 1] * linv);
            }
        }
    }
}

// ---------------- launcher ----------------
extern "C" void kernel_launch(void* const* d_in, const int* in_sizes, int n_in,
                              void* d_out, int out_size) {
    const float* ze   = (const float*)d_in[0];
    const float* temp = (const float*)d_in[1];
    const float* U    = (const float*)d_in[2];
    const float* book = (const float*)d_in[3];
    const float* lpq  = (const float*)d_in[4];
    float* out = (float*)d_out;

    static int attr_done = 0;
    if (!attr_done) {
        cudaFuncSetAttribute(k_gemm1, cudaFuncAttributeMaxDynamicSharedMemorySize, G1_SMEM);
        cudaFuncSetAttribute(k_gemm2, cudaFuncAttributeMaxDynamicSharedMemorySize, G2_SMEM);
        attr_done = 1;
    }

    k_prep_book<<<BOOK,   NDIM>>>(book);
    k_prep_ze  <<<N_ROWS, NDIM>>>(ze);
    k_scalar<<<1, 1>>>(lpq, out);
    k_gemm1<<<dim3(CBLK, N_ROWS / 128), 256, G1_SMEM>>>(U, temp, lpq, out);
    k_reduce<<<(N_ROWS * 32 + 255) / 256, 256>>>();
    k_gemm2<<<dim3(NDIM / 128, N_ROWS / 128), 256, G2_SMEM>>>(out);
}

// round 13
// speedup vs baseline: 1.6974x; 1.2388x over previous
#include <cuda_runtime.h>
#include <cuda_fp16.h>
#include <math.h>

#define N_ROWS 38912
#define NDIM   256
#define BOOK   2048
#define CBLK   16
#define PQ_IDX 9961472
#define LG_OFF 9961473
#define EPSF   1e-10f

// ---------------- device scratch ----------------
__device__ __half g_Ph[(size_t)N_ROWS * BOOK];
__device__ __half g_zeh[(size_t)N_ROWS * NDIM];
__device__ __half g_zel[(size_t)N_ROWS * NDIM];
__device__ __half g_bookh[BOOK * NDIM];
__device__ __half g_bookl[BOOK * NDIM];
__device__ __half g_bth[NDIM * BOOK];   // book^T hi: [dim][book]
__device__ float  g_zn[N_ROWS];
__device__ float  g_bn[BOOK];
__device__ float  g_pm[(size_t)N_ROWS * CBLK];
__device__ float  g_linv[N_ROWS];

// ---------------- helpers ----------------
__device__ __forceinline__ unsigned sptr(const void* p) {
    return (unsigned)__cvta_generic_to_shared(p);
}
__device__ __forceinline__ void ldsm4(unsigned addr, unsigned& r0, unsigned& r1,
                                      unsigned& r2, unsigned& r3) {
    asm volatile("ldmatrix.sync.aligned.m8n8.x4.shared.b16 {%0,%1,%2,%3}, [%4];"
                 : "=r"(r0), "=r"(r1), "=r"(r2), "=r"(r3) : "r"(addr));
}
__device__ __forceinline__ void mma16816(float* c, const unsigned* a,
                                         unsigned b0, unsigned b1) {
    asm volatile(
        "mma.sync.aligned.m16n8k16.row.col.f32.f16.f16.f32 "
        "{%0,%1,%2,%3}, {%4,%5,%6,%7}, {%8,%9}, {%0,%1,%2,%3};"
        : "+f"(c[0]), "+f"(c[1]), "+f"(c[2]), "+f"(c[3])
        : "r"(a[0]), "r"(a[1]), "r"(a[2]), "r"(a[3]), "r"(b0), "r"(b1));
}
__device__ __forceinline__ void cpa16(unsigned dst, const void* src) {
    asm volatile("cp.async.cg.shared.global [%0], [%1], 16;" :: "r"(dst), "l"(src) : "memory");
}
#define CP_COMMIT() asm volatile("cp.async.commit_group;" ::: "memory")
#define CP_WAIT(n)  asm volatile("cp.async.wait_group %0;" :: "n"(n) : "memory")

// ---------------- K0a: book prep (hi/lo + transpose-hi + norms) ----------------
__global__ void k_prep_book(const float* __restrict__ book) {
    int r = blockIdx.x, t = threadIdx.x;   // 2048 x 256
    size_t idx = (size_t)r * NDIM + t;
    float v = book[idx];
    __half h = __float2half_rn(v);
    __half l = __float2half_rn(v - __half2float(h));
    g_bookh[idx] = h;  g_bookl[idx] = l;
    g_bth[(size_t)t * BOOK + r] = h;
    float s = v * v;
    #pragma unroll
    for (int o = 16; o; o >>= 1) s += __shfl_xor_sync(0xffffffffu, s, o);
    __shared__ float red[8];
    if ((t & 31) == 0) red[t >> 5] = s;
    __syncthreads();
    if (t == 0) {
        float tot = 0.f;
        #pragma unroll
        for (int i = 0; i < 8; i++) tot += red[i];
        g_bn[r] = tot;
    }
}

// ---------------- K0b: ze prep ----------------
__global__ void k_prep_ze(const float* __restrict__ ze) {
    int r = blockIdx.x, t = threadIdx.x;
    size_t idx = (size_t)r * NDIM + t;
    float v = ze[idx];
    __half h = __float2half_rn(v);
    g_zeh[idx] = h;
    g_zel[idx] = __float2half_rn(v - __half2float(h));
    float s = v * v;
    #pragma unroll
    for (int o = 16; o; o >>= 1) s += __shfl_xor_sync(0xffffffffu, s, o);
    __shared__ float red[8];
    if ((t & 31) == 0) red[t >> 5] = s;
    __syncthreads();
    if (t == 0) {
        float tot = 0.f;
        #pragma unroll
        for (int i = 0; i < 8; i++) tot += red[i];
        g_zn[r] = tot;
    }
}

__global__ void k_scalar(const float* __restrict__ lpqP, float* __restrict__ out) {
    out[PQ_IDX] = 0.5f / fmaxf(expf(lpqP[0]), EPSF);
}

// ---------------- K1: pipelined mma.sync GEMM1 (3 fused passes, k=64 chunks) ----------------
// stage: A 128x72h = 18432B + B 128x72h = 18432B; 3 stages; then pm_s, bn_s
#define G1_STAGE 36864
#define G1_SMEM  (3 * G1_STAGE + 1024)

__global__ void __launch_bounds__(256, 2) k_gemm1(
    const float* __restrict__ U, const float* __restrict__ tempP,
    const float* __restrict__ lpqP, float* __restrict__ out)
{
    extern __shared__ __align__(1024) char smem[];
    float* pm_s = (float*)(smem + 3 * G1_STAGE);
    float* bn_s = (float*)(smem + 3 * G1_STAGE + 512);
    const unsigned sb = sptr(smem);
    const int t = threadIdx.x, lane = t & 31, warp = t >> 5;
    const int ct = blockIdx.x, rt = blockIdx.y;
    const int rowBase = rt * 128, colBase = ct * 128;
    const int wr = warp >> 1, wc = warp & 1;

    if (t < 128) bn_s[t] = g_bn[colBase + t];

    float acc[2][8][4];
    #pragma unroll
    for (int i = 0; i < 2; i++)
        #pragma unroll
        for (int j = 0; j < 8; j++)
            #pragma unroll
            for (int c = 0; c < 4; c++) acc[i][j][c] = 0.f;

    // chunk c in [0,12): pass = c/4 -> (zh.bh, zh.bl, zl.bh); kc = (c&3)*64
    auto fill = [&](int c, int s) {
        const __half* Ag = (c < 8) ? g_zeh : g_zel;
        const __half* Bg = (c >= 4 && c < 8) ? g_bookl : g_bookh;
        const int kc = (c & 3) * 64;
        unsigned ab = sb + s * G1_STAGE;
        unsigned bb = ab + 18432;
        #pragma unroll
        for (int i = 0; i < 4; i++) {
            int id = t + 256 * i;          // 0..1023
            int r = id >> 3, cc = id & 7;
            cpa16(ab + r * 144 + cc * 16, &Ag[(size_t)(rowBase + r) * NDIM + kc + cc * 8]);
            cpa16(bb + r * 144 + cc * 16, &Bg[(size_t)(colBase + r) * NDIM + kc + cc * 8]);
        }
        CP_COMMIT();
    };

    fill(0, 0); fill(1, 1); fill(2, 2);

    for (int it = 0; it < 12; it++) {
        const int s = it % 3;
        CP_WAIT(2);
        __syncthreads();
        const unsigned aB = sb + s * G1_STAGE;
        const unsigned bB = aB + 18432;
        #pragma unroll
        for (int sub = 0; sub < 4; sub++) {
            const int kb = sub * 16;
            unsigned a[2][4], b[4][4];
            #pragma unroll
            for (int i = 0; i < 2; i++)
                ldsm4(aB + ((wr * 32 + i * 16 + (lane & 15)) * 72 + kb + (lane >> 4) * 8) * 2,
                      a[i][0], a[i][1], a[i][2], a[i][3]);
            #pragma unroll
            for (int jj = 0; jj < 4; jj++)
                ldsm4(bB + ((wc * 64 + jj * 16 + (lane & 7) + (lane >> 4) * 8) * 72
                            + kb + ((lane >> 3) & 1) * 8) * 2,
                      b[jj][0], b[jj][1], b[jj][2], b[jj][3]);
            #pragma unroll
            for (int i = 0; i < 2; i++)
                #pragma unroll
                for (int j = 0; j < 8; j++)
                    mma16816(acc[i][j], a[i], b[j >> 1][(j & 1) * 2], b[j >> 1][(j & 1) * 2 + 1]);
        }
        __syncthreads();
        if (it + 3 < 12) fill(it + 3, s); else CP_COMMIT();
    }

    // ---------------- epilogue ----------------
    const float pq   = 0.5f / fmaxf(expf(lpqP[0]), EPSF);
    const float invT = 1.0f / tempP[0];
    float* __restrict__ outLg = out + LG_OFF;   // odd float offset -> scalar stores only

    float rmax[2][2] = {{-INFINITY, -INFINITY}, {-INFINITY, -INFINITY}};

    // pass 1: logits -> gmem, y kept in acc, row max.
    // gumbel inner log: fast __logf; exact logf only for u > 0.999 (row-max candidates)
    #pragma unroll
    for (int i = 0; i < 2; i++) {
        #pragma unroll
        for (int h = 0; h < 2; h++) {
            const int rl = wr * 32 + i * 16 + (lane >> 2) + h * 8;
            const int grow = rowBase + rl;
            const float zn = g_zn[grow];
            float* __restrict__ lgrow = outLg + (size_t)grow * BOOK + colBase;
            const float* __restrict__ urow = U + (size_t)grow * BOOK + colBase;
            #pragma unroll
            for (int j = 0; j < 8; j++) {
                const int cl = wc * 64 + j * 8 + (lane & 3) * 2;
                float d0 = acc[i][j][2 * h], d1 = acc[i][j][2 * h + 1];
                float lg0 = fmaf(2.f, d0, -(zn + bn_s[cl]))     * pq;
                float lg1 = fmaf(2.f, d1, -(zn + bn_s[cl + 1])) * pq;
                lgrow[cl]     = lg0;
                lgrow[cl + 1] = lg1;
                float2 u2 = *(const float2*)&urow[cl];
                float w0 = -__logf(u2.x + EPSF) + EPSF;
                float w1 = -__logf(u2.y + EPSF) + EPSF;
                if (u2.x > 0.999f) w0 = -logf(u2.x + EPSF) + EPSF;
                if (u2.y > 0.999f) w1 = -logf(u2.y + EPSF) + EPSF;
                float y0 = (lg0 - __logf(w0)) * invT;
                float y1 = (lg1 - __logf(w1)) * invT;
                acc[i][j][2 * h]     = y0;
                acc[i][j][2 * h + 1] = y1;
                rmax[i][h] = fmaxf(rmax[i][h], fmaxf(y0, y1));
            }
        }
    }
    // reduce row max within quad, then across the two col-half warps
    #pragma unroll
    for (int i = 0; i < 2; i++)
        #pragma unroll
        for (int h = 0; h < 2; h++) {
            float m = rmax[i][h];
            m = fmaxf(m, __shfl_xor_sync(0xffffffffu, m, 1));
            m = fmaxf(m, __shfl_xor_sync(0xffffffffu, m, 2));
            rmax[i][h] = m;
        }
    if (wc == 0 && (lane & 3) == 0) {
        #pragma unroll
        for (int i = 0; i < 2; i++)
            #pragma unroll
            for (int h = 0; h < 2; h++)
                pm_s[wr * 32 + i * 16 + (lane >> 2) + h * 8] = rmax[i][h];
    }
    __syncthreads();
    if (wc == 1 && (lane & 3) == 0) {
        #pragma unroll
        for (int i = 0; i < 2; i++)
            #pragma unroll
            for (int h = 0; h < 2; h++) {
                int idx = wr * 32 + i * 16 + (lane >> 2) + h * 8;
                pm_s[idx] = fmaxf(pm_s[idx], rmax[i][h]);
            }
    }
    __syncthreads();

    // pass 2: P' = exp(y - pm_tile) as half2 -> g_Ph (global rescale + sum in k_reduce)
    #pragma unroll
    for (int i = 0; i < 2; i++) {
        #pragma unroll
        for (int h = 0; h < 2; h++) {
            const int rl = wr * 32 + i * 16 + (lane >> 2) + h * 8;
            const int grow = rowBase + rl;
            const float pm = pm_s[rl];
            __half* __restrict__ prow = g_Ph + (size_t)grow * BOOK + colBase;
            #pragma unroll
            for (int j = 0; j < 8; j++) {
                const int cl = wc * 64 + j * 8 + (lane & 3) * 2;
                __half2 p = __floats2half2_rn(__expf(acc[i][j][2 * h] - pm),
                                              __expf(acc[i][j][2 * h + 1] - pm));
                *(__half2*)&prow[cl] = p;
            }
        }
    }
    if (t < 128) g_pm[(size_t)(rowBase + t) * CBLK + ct] = pm_s[t];
}

// ---------------- K2: warp-per-row global rescale of P + 1/L ----------------
__global__ void k_reduce() {
    int gw = (blockIdx.x * blockDim.x + threadIdx.x) >> 5;
    int lane = threadIdx.x & 31;
    if (gw >= N_ROWS) return;
    size_t r = gw;
    float pm = (lane < CBLK) ? g_pm[r * CBLK + lane] : -INFINITY;
    float m = pm;
    #pragma unroll
    for (int o = 16; o; o >>= 1) m = fmaxf(m, __shfl_xor_sync(0xffffffffu, m, o));
    float sc = __expf(pm - m);           // valid for lanes 0..15 (one per 128-col block)
    uint4* row = (uint4*)(g_Ph + r * BOOK);
    float s = 0.f;
    #pragma unroll
    for (int v = 0; v < 8; v++) {
        uint4 q = row[v * 32 + lane];    // cols (v*32+lane)*8 .. +8
        float scb = __shfl_sync(0xffffffffu, sc, v * 2 + (lane >> 4));
        __half2 hs = __float2half2_rn(scb);
        __half2 h0 = __hmul2(*(__half2*)&q.x, hs);
        __half2 h1 = __hmul2(*(__half2*)&q.y, hs);
        __half2 h2 = __hmul2(*(__half2*)&q.z, hs);
        __half2 h3 = __hmul2(*(__half2*)&q.w, hs);
        float2 f0 = __half22float2(h0), f1 = __half22float2(h1);
        float2 f2 = __half22float2(h2), f3 = __half22float2(h3);
        s += (f0.x + f0.y) + (f1.x + f1.y) + (f2.x + f2.y) + (f3.x + f3.y);
        q.x = *(unsigned*)&h0; q.y = *(unsigned*)&h1;
        q.z = *(unsigned*)&h2; q.w = *(unsigned*)&h3;
        row[v * 32 + lane] = q;
    }
    #pragma unroll
    for (int o = 16; o; o >>= 1) s += __shfl_xor_sync(0xffffffffu, s, o);
    if (lane == 0) g_linv[r] = 1.f / s;
}

// ---------------- K3: pipelined mma.sync GEMM2 (zq = P@book, hi only, k=64) ----------------
// stage: A 18432B + B 18432B; 3 stages
#define G2_STAGE 36864
#define G2_SMEM  (3 * G2_STAGE)

__global__ void __launch_bounds__(256, 2) k_gemm2(float* __restrict__ out) {
    extern __shared__ __align__(1024) char smem[];
    const unsigned sb = sptr(smem);
    const int t = threadIdx.x, lane = t & 31, warp = t >> 5;
    const int rowBase = blockIdx.y * 128, dimBase = blockIdx.x * 128;
    const int wr = warp >> 1, wc = warp & 1;

    float acc[2][8][4];
    #pragma unroll
    for (int i = 0; i < 2; i++)
        #pragma unroll
        for (int j = 0; j < 8; j++)
            #pragma unroll
            for (int c = 0; c < 4; c++) acc[i][j][c] = 0.f;

    auto fill = [&](int c, int s) {
        const int kc = c * 64;
        unsigned ab = sb + s * G2_STAGE;
        unsigned bb = ab + 18432;
        #pragma unroll
        for (int i = 0; i < 4; i++) {
            int id = t + 256 * i;
            int r = id >> 3, cc = id & 7;
            cpa16(ab + r * 144 + cc * 16, &g_Ph [(size_t)(rowBase + r) * BOOK + kc + cc * 8]);
            cpa16(bb + r * 144 + cc * 16, &g_bth[(size_t)(dimBase + r) * BOOK + kc + cc * 8]);
        }
        CP_COMMIT();
    };

    fill(0, 0); fill(1, 1); fill(2, 2);

    for (int it = 0; it < 32; it++) {
        const int s = it % 3;
        CP_WAIT(2);
        __syncthreads();
        const unsigned aB = sb + s * G2_STAGE;
        const unsigned bB = aB + 18432;
        #pragma unroll
        for (int sub = 0; sub < 4; sub++) {
            const int kb = sub * 16;
            unsigned a[2][4], b[4][4];
            #pragma unroll
            for (int i = 0; i < 2; i++)
                ldsm4(aB + ((wr * 32 + i * 16 + (lane & 15)) * 72 + kb + (lane >> 4) * 8) * 2,
                      a[i][0], a[i][1], a[i][2], a[i][3]);
            #pragma unroll
            for (int jj = 0; jj < 4; jj++)
                ldsm4(bB + ((wc * 64 + jj * 16 + (lane & 7) + (lane >> 4) * 8) * 72
                            + kb + ((lane >> 3) & 1) * 8) * 2,
                      b[jj][0], b[jj][1], b[jj][2], b[jj][3]);
            #pragma unroll
            for (int i = 0; i < 2; i++)
                #pragma unroll
                for (int j = 0; j < 8; j++)
                    mma16816(acc[i][j], a[i], b[j >> 1][(j & 1) * 2], b[j >> 1][(j & 1) * 2 + 1]);
        }
        __syncthreads();
        if (it + 3 < 32) fill(it + 3, s); else CP_COMMIT();
    }

    // epilogue: zq = acc * (1/L), float2 stores (even offsets; out base aligned)
    #pragma unroll
    for (int i = 0; i < 2; i++) {
        #pragma unroll
        for (int h = 0; h < 2; h++) {
            const int rl = wr * 32 + i * 16 + (lane >> 2) + h * 8;
            const int grow = rowBase + rl;
            const float linv = g_linv[grow];
            float* __restrict__ orow = out + (size_t)grow * NDIM + dimBase;
            #pragma unroll
            for (int j = 0; j < 8; j++) {
                const int cl = wc * 64 + j * 8 + (lane & 3) * 2;
                *(float2*)&orow[cl] = make_float2(acc[i][j][2 * h] * linv,
                                                  acc[i][j][2 * h + 1] * linv);
            }
        }
    }
}

// ---------------- launcher ----------------
extern "C" void kernel_launch(void* const* d_in, const int* in_sizes, int n_in,
                              void* d_out, int out_size) {
    const float* ze   = (const float*)d_in[0];
    const float* temp = (const float*)d_in[1];
    const float* U    = (const float*)d_in[2];
    const float* book = (const float*)d_in[3];
    const float* lpq  = (const float*)d_in[4];
    float* out = (float*)d_out;

    static int attr_done = 0;
    if (!attr_done) {
        cudaFuncSetAttribute(k_gemm1, cudaFuncAttributeMaxDynamicSharedMemorySize, G1_SMEM);
        cudaFuncSetAttribute(k_gemm2, cudaFuncAttributeMaxDynamicSharedMemorySize, G2_SMEM);
        attr_done = 1;
    }

    k_prep_book<<<BOOK,   NDIM>>>(book);
    k_prep_ze  <<<N_ROWS, NDIM>>>(ze);
    k_scalar<<<1, 1>>>(lpq, out);
    k_gemm1<<<dim3(CBLK, N_ROWS / 128), 256, G1_SMEM>>>(U, temp, lpq, out);
    k_reduce<<<(N_ROWS * 32 + 255) / 256, 256>>>();
    k_gemm2<<<dim3(NDIM / 128, N_ROWS / 128), 256, G2_SMEM>>>(out);
}

// round 14
// speedup vs baseline: 1.9698x; 1.1605x over previous
#include <cuda_runtime.h>
#include <cuda_fp16.h>
#include <math.h>

#define N_ROWS 38912
#define NDIM   256
#define BOOK   2048
#define CBLK   16
#define PQ_IDX 9961472
#define LG_OFF 9961473
#define EPSF   1e-10f

// ---------------- device scratch ----------------
__device__ __half g_Ph[(size_t)N_ROWS * BOOK];
__device__ __half g_zeh[(size_t)N_ROWS * NDIM];
__device__ __half g_bookh[BOOK * NDIM];
__device__ __half g_bookl[BOOK * NDIM];
__device__ __half g_bth[NDIM * BOOK];   // book^T hi: [dim][book]
__device__ float  g_zn[N_ROWS];
__device__ float  g_bn[BOOK];
__device__ float  g_pm[(size_t)N_ROWS * CBLK];
__device__ float  g_linv[N_ROWS];

// ---------------- helpers ----------------
__device__ __forceinline__ unsigned sptr(const void* p) {
    return (unsigned)__cvta_generic_to_shared(p);
}
__device__ __forceinline__ void ldsm4(unsigned addr, unsigned& r0, unsigned& r1,
                                      unsigned& r2, unsigned& r3) {
    asm volatile("ldmatrix.sync.aligned.m8n8.x4.shared.b16 {%0,%1,%2,%3}, [%4];"
                 : "=r"(r0), "=r"(r1), "=r"(r2), "=r"(r3) : "r"(addr));
}
__device__ __forceinline__ void mma16816(float* c, const unsigned* a,
                                         unsigned b0, unsigned b1) {
    asm volatile(
        "mma.sync.aligned.m16n8k16.row.col.f32.f16.f16.f32 "
        "{%0,%1,%2,%3}, {%4,%5,%6,%7}, {%8,%9}, {%0,%1,%2,%3};"
        : "+f"(c[0]), "+f"(c[1]), "+f"(c[2]), "+f"(c[3])
        : "r"(a[0]), "r"(a[1]), "r"(a[2]), "r"(a[3]), "r"(b0), "r"(b1));
}
__device__ __forceinline__ void cpa16(unsigned dst, const void* src) {
    asm volatile("cp.async.cg.shared.global [%0], [%1], 16;" :: "r"(dst), "l"(src) : "memory");
}
#define CP_COMMIT() asm volatile("cp.async.commit_group;" ::: "memory")
#define CP_WAIT(n)  asm volatile("cp.async.wait_group %0;" :: "n"(n) : "memory")

// ---------------- K0a: book prep (hi/lo + transpose-hi + norms) ----------------
__global__ void k_prep_book(const float* __restrict__ book) {
    int r = blockIdx.x, t = threadIdx.x;   // 2048 x 256
    size_t idx = (size_t)r * NDIM + t;
    float v = book[idx];
    __half h = __float2half_rn(v);
    __half l = __float2half_rn(v - __half2float(h));
    g_bookh[idx] = h;  g_bookl[idx] = l;
    g_bth[(size_t)t * BOOK + r] = h;
    float s = v * v;
    #pragma unroll
    for (int o = 16; o; o >>= 1) s += __shfl_xor_sync(0xffffffffu, s, o);
    __shared__ float red[8];
    if ((t & 31) == 0) red[t >> 5] = s;
    __syncthreads();
    if (t == 0) {
        float tot = 0.f;
        #pragma unroll
        for (int i = 0; i < 8; i++) tot += red[i];
        g_bn[r] = tot;
    }
}

// ---------------- K0b: ze prep (hi only + norms) ----------------
__global__ void k_prep_ze(const float* __restrict__ ze) {
    int r = blockIdx.x, t = threadIdx.x;
    size_t idx = (size_t)r * NDIM + t;
    float v = ze[idx];
    g_zeh[idx] = __float2half_rn(v);
    float s = v * v;
    #pragma unroll
    for (int o = 16; o; o >>= 1) s += __shfl_xor_sync(0xffffffffu, s, o);
    __shared__ float red[8];
    if ((t & 31) == 0) red[t >> 5] = s;
    __syncthreads();
    if (t == 0) {
        float tot = 0.f;
        #pragma unroll
        for (int i = 0; i < 8; i++) tot += red[i];
        g_zn[r] = tot;
    }
}

__global__ void k_scalar(const float* __restrict__ lpqP, float* __restrict__ out) {
    out[PQ_IDX] = 0.5f / fmaxf(expf(lpqP[0]), EPSF);
}

// ---------------- K1: pipelined mma.sync GEMM1 (2 fused passes, k=64 chunks) ----------------
// stage: A 128x72h = 18432B + B 128x72h = 18432B; 3 stages; then pm_s, bn_s
#define G1_STAGE 36864
#define G1_SMEM  (3 * G1_STAGE + 1024)

__global__ void __launch_bounds__(256, 2) k_gemm1(
    const float* __restrict__ U, const float* __restrict__ tempP,
    const float* __restrict__ lpqP, float* __restrict__ out)
{
    extern __shared__ __align__(1024) char smem[];
    float* pm_s = (float*)(smem + 3 * G1_STAGE);
    float* bn_s = (float*)(smem + 3 * G1_STAGE + 512);
    const unsigned sb = sptr(smem);
    const int t = threadIdx.x, lane = t & 31, warp = t >> 5;
    const int ct = blockIdx.x, rt = blockIdx.y;
    const int rowBase = rt * 128, colBase = ct * 128;
    const int wr = warp >> 1, wc = warp & 1;

    if (t < 128) bn_s[t] = g_bn[colBase + t];

    float acc[2][8][4];
    #pragma unroll
    for (int i = 0; i < 2; i++)
        #pragma unroll
        for (int j = 0; j < 8; j++)
            #pragma unroll
            for (int c = 0; c < 4; c++) acc[i][j][c] = 0.f;

    // chunk c in [0,8): pass = c/4 -> (zh.bh, zh.bl); kc = (c&3)*64
    auto fill = [&](int c, int s) {
        const __half* Bg = (c >= 4) ? g_bookl : g_bookh;
        const int kc = (c & 3) * 64;
        unsigned ab = sb + s * G1_STAGE;
        unsigned bb = ab + 18432;
        #pragma unroll
        for (int i = 0; i < 4; i++) {
            int id = t + 256 * i;          // 0..1023
            int r = id >> 3, cc = id & 7;
            cpa16(ab + r * 144 + cc * 16, &g_zeh[(size_t)(rowBase + r) * NDIM + kc + cc * 8]);
            cpa16(bb + r * 144 + cc * 16, &Bg[(size_t)(colBase + r) * NDIM + kc + cc * 8]);
        }
        CP_COMMIT();
    };

    fill(0, 0); fill(1, 1); fill(2, 2);

    for (int it = 0; it < 8; it++) {
        const int s = it % 3;
        CP_WAIT(2);
        __syncthreads();
        const unsigned aB = sb + s * G1_STAGE;
        const unsigned bB = aB + 18432;
        #pragma unroll
        for (int sub = 0; sub < 4; sub++) {
            const int kb = sub * 16;
            unsigned a[2][4], b[4][4];
            #pragma unroll
            for (int i = 0; i < 2; i++)
                ldsm4(aB + ((wr * 32 + i * 16 + (lane & 15)) * 72 + kb + (lane >> 4) * 8) * 2,
                      a[i][0], a[i][1], a[i][2], a[i][3]);
            #pragma unroll
            for (int jj = 0; jj < 4; jj++)
                ldsm4(bB + ((wc * 64 + jj * 16 + (lane & 7) + (lane >> 4) * 8) * 72
                            + kb + ((lane >> 3) & 1) * 8) * 2,
                      b[jj][0], b[jj][1], b[jj][2], b[jj][3]);
            #pragma unroll
            for (int i = 0; i < 2; i++)
                #pragma unroll
                for (int j = 0; j < 8; j++)
                    mma16816(acc[i][j], a[i], b[j >> 1][(j & 1) * 2], b[j >> 1][(j & 1) * 2 + 1]);
        }
        __syncthreads();
        if (it + 3 < 8) fill(it + 3, s); else CP_COMMIT();
    }

    // ---------------- epilogue ----------------
    const float pq   = 0.5f / fmaxf(expf(lpqP[0]), EPSF);
    const float invT = 1.0f / tempP[0];
    float* __restrict__ outLg = out + LG_OFF;   // odd float offset -> scalar stores only

    float rmax[2][2] = {{-INFINITY, -INFINITY}, {-INFINITY, -INFINITY}};

    // pass 1: logits -> gmem, y kept in acc, row max.
    // gumbel inner log: fast __logf; exact logf only for u > 0.999 (row-max candidates)
    #pragma unroll
    for (int i = 0; i < 2; i++) {
        #pragma unroll
        for (int h = 0; h < 2; h++) {
            const int rl = wr * 32 + i * 16 + (lane >> 2) + h * 8;
            const int grow = rowBase + rl;
            const float zn = g_zn[grow];
            float* __restrict__ lgrow = outLg + (size_t)grow * BOOK + colBase;
            const float* __restrict__ urow = U + (size_t)grow * BOOK + colBase;
            #pragma unroll
            for (int j = 0; j < 8; j++) {
                const int cl = wc * 64 + j * 8 + (lane & 3) * 2;
                float d0 = acc[i][j][2 * h], d1 = acc[i][j][2 * h + 1];
                float lg0 = fmaf(2.f, d0, -(zn + bn_s[cl]))     * pq;
                float lg1 = fmaf(2.f, d1, -(zn + bn_s[cl + 1])) * pq;
                lgrow[cl]     = lg0;
                lgrow[cl + 1] = lg1;
                float2 u2 = *(const float2*)&urow[cl];
                float w0 = -__logf(u2.x + EPSF) + EPSF;
                float w1 = -__logf(u2.y + EPSF) + EPSF;
                if (u2.x > 0.999f) w0 = -logf(u2.x + EPSF) + EPSF;
                if (u2.y > 0.999f) w1 = -logf(u2.y + EPSF) + EPSF;
                float y0 = (lg0 - __logf(w0)) * invT;
                float y1 = (lg1 - __logf(w1)) * invT;
                acc[i][j][2 * h]     = y0;
                acc[i][j][2 * h + 1] = y1;
                rmax[i][h] = fmaxf(rmax[i][h], fmaxf(y0, y1));
            }
        }
    }
    // reduce row max within quad, then across the two col-half warps
    #pragma unroll
    for (int i = 0; i < 2; i++)
        #pragma unroll
        for (int h = 0; h < 2; h++) {
            float m = rmax[i][h];
            m = fmaxf(m, __shfl_xor_sync(0xffffffffu, m, 1));
            m = fmaxf(m, __shfl_xor_sync(0xffffffffu, m, 2));
            rmax[i][h] = m;
        }
    if (wc == 0 && (lane & 3) == 0) {
        #pragma unroll
        for (int i = 0; i < 2; i++)
            #pragma unroll
            for (int h = 0; h < 2; h++)
                pm_s[wr * 32 + i * 16 + (lane >> 2) + h * 8] = rmax[i][h];
    }
    __syncthreads();
    if (wc == 1 && (lane & 3) == 0) {
        #pragma unroll
        for (int i = 0; i < 2; i++)
            #pragma unroll
            for (int h = 0; h < 2; h++) {
                int idx = wr * 32 + i * 16 + (lane >> 2) + h * 8;
                pm_s[idx] = fmaxf(pm_s[idx], rmax[i][h]);
            }
    }
    __syncthreads();

    // pass 2: P' = exp(y - pm_tile) as half2 -> g_Ph (global rescale + sum in k_reduce)
    #pragma unroll
    for (int i = 0; i < 2; i++) {
        #pragma unroll
        for (int h = 0; h < 2; h++) {
            const int rl = wr * 32 + i * 16 + (lane >> 2) + h * 8;
            const int grow = rowBase + rl;
            const float pm = pm_s[rl];
            __half* __restrict__ prow = g_Ph + (size_t)grow * BOOK + colBase;
            #pragma unroll
            for (int j = 0; j < 8; j++) {
                const int cl = wc * 64 + j * 8 + (lane & 3) * 2;
                __half2 p = __floats2half2_rn(__expf(acc[i][j][2 * h] - pm),
                                              __expf(acc[i][j][2 * h + 1] - pm));
                *(__half2*)&prow[cl] = p;
            }
        }
    }
    if (t < 128) g_pm[(size_t)(rowBase + t) * CBLK + ct] = pm_s[t];
}

// ---------------- K2: warp-per-row global rescale of P + 1/L ----------------
__global__ void k_reduce() {
    int gw = (blockIdx.x * blockDim.x + threadIdx.x) >> 5;
    int lane = threadIdx.x & 31;
    if (gw >= N_ROWS) return;
    size_t r = gw;
    float pm = (lane < CBLK) ? g_pm[r * CBLK + lane] : -INFINITY;
    float m = pm;
    #pragma unroll
    for (int o = 16; o; o >>= 1) m = fmaxf(m, __shfl_xor_sync(0xffffffffu, m, o));
    float sc = __expf(pm - m);           // valid for lanes 0..15 (one per 128-col block)
    uint4* row = (uint4*)(g_Ph + r * BOOK);
    float s = 0.f;
    #pragma unroll
    for (int v = 0; v < 8; v++) {
        uint4 q = row[v * 32 + lane];    // cols (v*32+lane)*8 .. +8
        float scb = __shfl_sync(0xffffffffu, sc, v * 2 + (lane >> 4));
        __half2 hs = __float2half2_rn(scb);
        __half2 h0 = __hmul2(*(__half2*)&q.x, hs);
        __half2 h1 = __hmul2(*(__half2*)&q.y, hs);
        __half2 h2 = __hmul2(*(__half2*)&q.z, hs);
        __half2 h3 = __hmul2(*(__half2*)&q.w, hs);
        float2 f0 = __half22float2(h0), f1 = __half22float2(h1);
        float2 f2 = __half22float2(h2), f3 = __half22float2(h3);
        s += (f0.x + f0.y) + (f1.x + f1.y) + (f2.x + f2.y) + (f3.x + f3.y);
        q.x = *(unsigned*)&h0; q.y = *(unsigned*)&h1;
        q.z = *(unsigned*)&h2; q.w = *(unsigned*)&h3;
        row[v * 32 + lane] = q;
    }
    #pragma unroll
    for (int o = 16; o; o >>= 1) s += __shfl_xor_sync(0xffffffffu, s, o);
    if (lane == 0) g_linv[r] = 1.f / s;
}

// ---------------- K3: pipelined mma.sync GEMM2 (zq = P@book, hi only, k=64) ----------------
// stage: A 18432B + B 18432B; 3 stages
#define G2_STAGE 36864
#define G2_SMEM  (3 * G2_STAGE)

__global__ void __launch_bounds__(256, 2) k_gemm2(float* __restrict__ out) {
    extern __shared__ __align__(1024) char smem[];
    const unsigned sb = sptr(smem);
    const int t = threadIdx.x, lane = t & 31, warp = t >> 5;
    const int rowBase = blockIdx.y * 128, dimBase = blockIdx.x * 128;
    const int wr = warp >> 1, wc = warp & 1;

    float acc[2][8][4];
    #pragma unroll
    for (int i = 0; i < 2; i++)
        #pragma unroll
        for (int j = 0; j < 8; j++)
            #pragma unroll
            for (int c = 0; c < 4; c++) acc[i][j][c] = 0.f;

    auto fill = [&](int c, int s) {
        const int kc = c * 64;
        unsigned ab = sb + s * G2_STAGE;
        unsigned bb = ab + 18432;
        #pragma unroll
        for (int i = 0; i < 4; i++) {
            int id = t + 256 * i;
            int r = id >> 3, cc = id & 7;
            cpa16(ab + r * 144 + cc * 16, &g_Ph [(size_t)(rowBase + r) * BOOK + kc + cc * 8]);
            cpa16(bb + r * 144 + cc * 16, &g_bth[(size_t)(dimBase + r) * BOOK + kc + cc * 8]);
        }
        CP_COMMIT();
    };

    fill(0, 0); fill(1, 1); fill(2, 2);

    for (int it = 0; it < 32; it++) {
        const int s = it % 3;
        CP_WAIT(2);
        __syncthreads();
        const unsigned aB = sb + s * G2_STAGE;
        const unsigned bB = aB + 18432;
        #pragma unroll
        for (int sub = 0; sub < 4; sub++) {
            const int kb = sub * 16;
            unsigned a[2][4], b[4][4];
            #pragma unroll
            for (int i = 0; i < 2; i++)
                ldsm4(aB + ((wr * 32 + i * 16 + (lane & 15)) * 72 + kb + (lane >> 4) * 8) * 2,
                      a[i][0], a[i][1], a[i][2], a[i][3]);
            #pragma unroll
            for (int jj = 0; jj < 4; jj++)
                ldsm4(bB + ((wc * 64 + jj * 16 + (lane & 7) + (lane >> 4) * 8) * 72
                            + kb + ((lane >> 3) & 1) * 8) * 2,
                      b[jj][0], b[jj][1], b[jj][2], b[jj][3]);
            #pragma unroll
            for (int i = 0; i < 2; i++)
                #pragma unroll
                for (int j = 0; j < 8; j++)
                    mma16816(acc[i][j], a[i], b[j >> 1][(j & 1) * 2], b[j >> 1][(j & 1) * 2 + 1]);
        }
        __syncthreads();
        if (it + 3 < 32) fill(it + 3, s); else CP_COMMIT();
    }

    // epilogue: zq = acc * (1/L), float2 stores (even offsets; out base aligned)
    #pragma unroll
    for (int i = 0; i < 2; i++) {
        #pragma unroll
        for (int h = 0; h < 2; h++) {
            const int rl = wr * 32 + i * 16 + (lane >> 2) + h * 8;
            const int grow = rowBase + rl;
            const float linv = g_linv[grow];
            float* __restrict__ orow = out + (size_t)grow * NDIM + dimBase;
            #pragma unroll
            for (int j = 0; j < 8; j++) {
                const int cl = wc * 64 + j * 8 + (lane & 3) * 2;
                *(float2*)&orow[cl] = make_float2(acc[i][j][2 * h] * linv,
                                                  acc[i][j][2 * h + 1] * linv);
            }
        }
    }
}

// ---------------- launcher ----------------
extern "C" void kernel_launch(void* const* d_in, const int* in_sizes, int n_in,
                              void* d_out, int out_size) {
    const float* ze   = (const float*)d_in[0];
    const float* temp = (const float*)d_in[1];
    const float* U    = (const float*)d_in[2];
    const float* book = (const float*)d_in[3];
    const float* lpq  = (const float*)d_in[4];
    float* out = (float*)d_out;

    static int attr_done = 0;
    if (!attr_done) {
        cudaFuncSetAttribute(k_gemm1, cudaFuncAttributeMaxDynamicSharedMemorySize, G1_SMEM);
        cudaFuncSetAttribute(k_gemm2, cudaFuncAttributeMaxDynamicSharedMemorySize, G2_SMEM);
        attr_done = 1;
    }

    k_prep_book<<<BOOK,   NDIM>>>(book);
    k_prep_ze  <<<N_ROWS, NDIM>>>(ze);
    k_scalar<<<1, 1>>>(lpq, out);
    k_gemm1<<<dim3(CBLK, N_ROWS / 128), 256, G1_SMEM>>>(U, temp, lpq, out);
    k_reduce<<<(N_ROWS * 32 + 255) / 256, 256>>>();
    k_gemm2<<<dim3(NDIM / 128, N_ROWS / 128), 256, G2_SMEM>>>(out);
}

// round 16
// speedup vs baseline: 2.0105x; 1.0207x over previous
#include <cuda_runtime.h>
#include <cuda_fp16.h>
#include <math.h>

#define N_ROWS 38912
#define NDIM   256
#define BOOK   2048
#define CBLK   16
#define PQ_IDX 9961472
#define LG_OFF 9961473
#define EPSF   1e-10f

// ---------------- device scratch ----------------
__device__ __half g_Ph[(size_t)N_ROWS * BOOK];
__device__ __half g_zeh[(size_t)N_ROWS * NDIM];
__device__ __half g_bookh[BOOK * NDIM];
__device__ __half g_bookl[BOOK * NDIM];
__device__ __half g_bth[NDIM * BOOK];   // book^T hi: [dim][book]
__device__ float  g_zn[N_ROWS];
__device__ float  g_bn[BOOK];
__device__ float  g_pm[(size_t)N_ROWS * CBLK];
__device__ float  g_linv[N_ROWS];

// ---------------- helpers ----------------
__device__ __forceinline__ unsigned sptr(const void* p) {
    return (unsigned)__cvta_generic_to_shared(p);
}
__device__ __forceinline__ void ldsm4(unsigned addr, unsigned& r0, unsigned& r1,
                                      unsigned& r2, unsigned& r3) {
    asm volatile("ldmatrix.sync.aligned.m8n8.x4.shared.b16 {%0,%1,%2,%3}, [%4];"
                 : "=r"(r0), "=r"(r1), "=r"(r2), "=r"(r3) : "r"(addr));
}
__device__ __forceinline__ void mma16816(float* c, const unsigned* a,
                                         unsigned b0, unsigned b1) {
    asm volatile(
        "mma.sync.aligned.m16n8k16.row.col.f32.f16.f16.f32 "
        "{%0,%1,%2,%3}, {%4,%5,%6,%7}, {%8,%9}, {%0,%1,%2,%3};"
        : "+f"(c[0]), "+f"(c[1]), "+f"(c[2]), "+f"(c[3])
        : "r"(a[0]), "r"(a[1]), "r"(a[2]), "r"(a[3]), "r"(b0), "r"(b1));
}
__device__ __forceinline__ void cpa16(unsigned dst, const void* src) {
    asm volatile("cp.async.cg.shared.global [%0], [%1], 16;" :: "r"(dst), "l"(src) : "memory");
}
#define CP_COMMIT() asm volatile("cp.async.commit_group;" ::: "memory")
#define CP_WAIT(n)  asm volatile("cp.async.wait_group %0;" :: "n"(n) : "memory")

__device__ __forceinline__ float2 ldcs2(const float* p) {
    float2 v;
    asm volatile("ld.global.cs.v2.f32 {%0,%1}, [%2];" : "=f"(v.x), "=f"(v.y) : "l"(p));
    return v;
}
__device__ __forceinline__ void stcs1(float* p, float v) {
    asm volatile("st.global.cs.f32 [%0], %1;" :: "l"(p), "f"(v));
}
__device__ __forceinline__ void pref_l2(const void* p) {
    asm volatile("prefetch.global.L2 [%0];" :: "l"(p));
}

// ---------------- K0a: book prep (hi/lo + transpose-hi + norms) ----------------
__global__ void k_prep_book(const float* __restrict__ book) {
    int r = blockIdx.x, t = threadIdx.x;   // 2048 x 256
    size_t idx = (size_t)r * NDIM + t;
    float v = book[idx];
    __half h = __float2half_rn(v);
    __half l = __float2half_rn(v - __half2float(h));
    g_bookh[idx] = h;  g_bookl[idx] = l;
    g_bth[(size_t)t * BOOK + r] = h;
    float s = v * v;
    #pragma unroll
    for (int o = 16; o; o >>= 1) s += __shfl_xor_sync(0xffffffffu, s, o);
    __shared__ float red[8];
    if ((t & 31) == 0) red[t >> 5] = s;
    __syncthreads();
    if (t == 0) {
        float tot = 0.f;
        #pragma unroll
        for (int i = 0; i < 8; i++) tot += red[i];
        g_bn[r] = tot;
    }
}

// ---------------- K0b: ze prep (hi only + norms) ----------------
__global__ void k_prep_ze(const float* __restrict__ ze) {
    int r = blockIdx.x, t = threadIdx.x;
    size_t idx = (size_t)r * NDIM + t;
    float v = ze[idx];
    g_zeh[idx] = __float2half_rn(v);
    float s = v * v;
    #pragma unroll
    for (int o = 16; o; o >>= 1) s += __shfl_xor_sync(0xffffffffu, s, o);
    __shared__ float red[8];
    if ((t & 31) == 0) red[t >> 5] = s;
    __syncthreads();
    if (t == 0) {
        float tot = 0.f;
        #pragma unroll
        for (int i = 0; i < 8; i++) tot += red[i];
        g_zn[r] = tot;
    }
}

__global__ void k_scalar(const float* __restrict__ lpqP, float* __restrict__ out) {
    out[PQ_IDX] = 0.5f / fmaxf(expf(lpqP[0]), EPSF);
}

// ---------------- K1: pipelined mma.sync GEMM1 (A shared across Bh/Bl, k=64) ----------------
// stage: A 18432B + Bh 18432B + Bl 18432B = 55296B; 2 stages; then pm_s, bn_s
#define G1_STAGE 55296
#define G1_SMEM  (2 * G1_STAGE + 1024)

__global__ void __launch_bounds__(256, 2) k_gemm1(
    const float* __restrict__ U, const float* __restrict__ tempP,
    const float* __restrict__ lpqP, float* __restrict__ out)
{
    extern __shared__ __align__(1024) char smem[];
    float* pm_s = (float*)(smem + 2 * G1_STAGE);
    float* bn_s = (float*)(smem + 2 * G1_STAGE + 512);
    const unsigned sb = sptr(smem);
    const int t = threadIdx.x, lane = t & 31, warp = t >> 5;
    const int ct = blockIdx.x, rt = blockIdx.y;
    const int rowBase = rt * 128, colBase = ct * 128;
    const int wr = warp >> 1, wc = warp & 1;

    if (t < 128) bn_s[t] = g_bn[colBase + t];

    float acc[2][8][4];
    #pragma unroll
    for (int i = 0; i < 2; i++)
        #pragma unroll
        for (int j = 0; j < 8; j++)
            #pragma unroll
            for (int c = 0; c < 4; c++) acc[i][j][c] = 0.f;

    // chunk c in [0,4): kc = c*64. Each stage holds A, Bh, Bl for one k-chunk.
    auto fill = [&](int c, int s) {
        const int kc = c * 64;
        unsigned ab  = sb + s * G1_STAGE;
        unsigned bhb = ab + 18432;
        unsigned blb = ab + 36864;
        #pragma unroll
        for (int i = 0; i < 4; i++) {
            int id = t + 256 * i;          // 0..1023
            int r = id >> 3, cc = id & 7;
            size_t ao = (size_t)(rowBase + r) * NDIM + kc + cc * 8;
            size_t bo = (size_t)(colBase + r) * NDIM + kc + cc * 8;
            cpa16(ab  + r * 144 + cc * 16, &g_zeh[ao]);
            cpa16(bhb + r * 144 + cc * 16, &g_bookh[bo]);
            cpa16(blb + r * 144 + cc * 16, &g_bookl[bo]);
        }
        CP_COMMIT();
    };

    fill(0, 0); fill(1, 1);

    for (int it = 0; it < 4; it++) {
        const int s = it & 1;
        CP_WAIT(1);
        __syncthreads();
        // prefetch this tile's U rows [it*32, it*32+32) into L2 (used in epilogue)
        if (t < 128)
            pref_l2(U + (size_t)(rowBase + it * 32 + (t >> 2)) * BOOK + colBase + (t & 3) * 32);
        const unsigned aB  = sb + s * G1_STAGE;
        const unsigned bhB = aB + 18432;
        const unsigned blB = aB + 36864;
        #pragma unroll
        for (int sub = 0; sub < 4; sub++) {
            const int kb = sub * 16;
            unsigned a[2][4], b[4][4];
            #pragma unroll
            for (int i = 0; i < 2; i++)
                ldsm4(aB + ((wr * 32 + i * 16 + (lane & 15)) * 72 + kb + (lane >> 4) * 8) * 2,
                      a[i][0], a[i][1], a[i][2], a[i][3]);
            const unsigned boff = ((wc * 64 + (lane & 7) + (lane >> 4) * 8) * 72
                                   + kb + ((lane >> 3) & 1) * 8) * 2;
            #pragma unroll
            for (int jj = 0; jj < 4; jj++)
                ldsm4(bhB + boff + jj * 16 * 72 * 2,
                      b[jj][0], b[jj][1], b[jj][2], b[jj][3]);
            #pragma unroll
            for (int i = 0; i < 2; i++)
                #pragma unroll
                for (int j = 0; j < 8; j++)
                    mma16816(acc[i][j], a[i], b[j >> 1][(j & 1) * 2], b[j >> 1][(j & 1) * 2 + 1]);
            #pragma unroll
            for (int jj = 0; jj < 4; jj++)
                ldsm4(blB + boff + jj * 16 * 72 * 2,
                      b[jj][0], b[jj][1], b[jj][2], b[jj][3]);
            #pragma unroll
            for (int i = 0; i < 2; i++)
                #pragma unroll
                for (int j = 0; j < 8; j++)
                    mma16816(acc[i][j], a[i], b[j >> 1][(j & 1) * 2], b[j >> 1][(j & 1) * 2 + 1]);
        }
        __syncthreads();
        if (it + 2 < 4) fill(it + 2, s); else CP_COMMIT();
    }

    // ---------------- epilogue ----------------
    const float pq   = 0.5f / fmaxf(expf(lpqP[0]), EPSF);
    const float invT = 1.0f / tempP[0];
    float* __restrict__ outLg = out + LG_OFF;   // odd float offset -> scalar stores only

    float rmax[2][2] = {{-INFINITY, -INFINITY}, {-INFINITY, -INFINITY}};

    // pass 1: logits -> gmem (streaming), y kept in acc, row max.
    // gumbel inner log: fast __logf; exact logf only for u > 0.999 (row-max candidates)
    #pragma unroll
    for (int i = 0; i < 2; i++) {
        #pragma unroll
        for (int h = 0; h < 2; h++) {
            const int rl = wr * 32 + i * 16 + (lane >> 2) + h * 8;
            const int grow = rowBase + rl;
            const float zn = g_zn[grow];
            float* __restrict__ lgrow = outLg + (size_t)grow * BOOK + colBase;
            const float* __restrict__ urow = U + (size_t)grow * BOOK + colBase;
            #pragma unroll
            for (int j = 0; j < 8; j++) {
                const int cl = wc * 64 + j * 8 + (lane & 3) * 2;
                float d0 = acc[i][j][2 * h], d1 = acc[i][j][2 * h + 1];
                float lg0 = fmaf(2.f, d0, -(zn + bn_s[cl]))     * pq;
                float lg1 = fmaf(2.f, d1, -(zn + bn_s[cl + 1])) * pq;
                stcs1(&lgrow[cl],     lg0);
                stcs1(&lgrow[cl + 1], lg1);
                float2 u2 = ldcs2(&urow[cl]);
                float w0 = -__logf(u2.x + EPSF) + EPSF;
                float w1 = -__logf(u2.y + EPSF) + EPSF;
                if (u2.x > 0.999f) w0 = -logf(u2.x + EPSF) + EPSF;
                if (u2.y > 0.999f) w1 = -logf(u2.y + EPSF) + EPSF;
                float y0 = (lg0 - __logf(w0)) * invT;
                float y1 = (lg1 - __logf(w1)) * invT;
                acc[i][j][2 * h]     = y0;
                acc[i][j][2 * h + 1] = y1;
                rmax[i][h] = fmaxf(rmax[i][h], fmaxf(y0, y1));
            }
        }
    }
    // reduce row max within quad, then across the two col-half warps
    #pragma unroll
    for (int i = 0; i < 2; i++)
        #pragma unroll
        for (int h = 0; h < 2; h++) {
            float m = rmax[i][h];
            m = fmaxf(m, __shfl_xor_sync(0xffffffffu, m, 1));
            m = fmaxf(m, __shfl_xor_sync(0xffffffffu, m, 2));
            rmax[i][h] = m;
        }
    if (wc == 0 && (lane & 3) == 0) {
        #pragma unroll
        for (int i = 0; i < 2; i++)
            #pragma unroll
            for (int h = 0; h < 2; h++)
                pm_s[wr * 32 + i * 16 + (lane >> 2) + h * 8] = rmax[i][h];
    }
    __syncthreads();
    if (wc == 1 && (lane & 3) == 0) {
        #pragma unroll
        for (int i = 0; i < 2; i++)
            #pragma unroll
            for (int h = 0; h < 2; h++) {
                int idx = wr * 32 + i * 16 + (lane >> 2) + h * 8;
                pm_s[idx] = fmaxf(pm_s[idx], rmax[i][h]);
            }
    }
    __syncthreads();

    // pass 2: P' = exp(y - pm_tile) as half2 -> g_Ph (global rescale + sum in k_reduce)
    #pragma unroll
    for (int i = 0; i < 2; i++) {
        #pragma unroll
        for (int h = 0; h < 2; h++) {
            const int rl = wr * 32 + i * 16 + (lane >> 2) + h * 8;
            const int grow = rowBase + rl;
            const float pm = pm_s[rl];
            __half* __restrict__ prow = g_Ph + (size_t)grow * BOOK + colBase;
            #pragma unroll
            for (int j = 0; j < 8; j++) {
                const int cl = wc * 64 + j * 8 + (lane & 3) * 2;
                __half2 p = __floats2half2_rn(__expf(acc[i][j][2 * h] - pm),
                                              __expf(acc[i][j][2 * h + 1] - pm));
                *(__half2*)&prow[cl] = p;
            }
        }
    }
    if (t < 128) g_pm[(size_t)(rowBase + t) * CBLK + ct] = pm_s[t];
}

// ---------------- K2: warp-per-row global rescale of P + 1/L ----------------
__global__ void k_reduce() {
    int gw = (blockIdx.x * blockDim.x + threadIdx.x) >> 5;
    int lane = threadIdx.x & 31;
    if (gw >= N_ROWS) return;
    size_t r = gw;
    float pm = (lane < CBLK) ? g_pm[r * CBLK + lane] : -INFINITY;
    float m = pm;
    #pragma unroll
    for (int o = 16; o; o >>= 1) m = fmaxf(m, __shfl_xor_sync(0xffffffffu, m, o));
    float sc = __expf(pm - m);           // valid for lanes 0..15 (one per 128-col block)
    uint4* row = (uint4*)(g_Ph + r * BOOK);
    float s = 0.f;
    #pragma unroll
    for (int v = 0; v < 8; v++) {
        uint4 q = row[v * 32 + lane];    // cols (v*32+lane)*8 .. +8
        float scb = __shfl_sync(0xffffffffu, sc, v * 2 + (lane >> 4));
        __half2 hs = __float2half2_rn(scb);
        __half2 h0 = __hmul2(*(__half2*)&q.x, hs);
        __half2 h1 = __hmul2(*(__half2*)&q.y, hs);
        __half2 h2 = __hmul2(*(__half2*)&q.z, hs);
        __half2 h3 = __hmul2(*(__half2*)&q.w, hs);
        float2 f0 = __half22float2(h0), f1 = __half22float2(h1);
        float2 f2 = __half22float2(h2), f3 = __half22float2(h3);
        s += (f0.x + f0.y) + (f1.x + f1.y) + (f2.x + f2.y) + (f3.x + f3.y);
        q.x = *(unsigned*)&h0; q.y = *(unsigned*)&h1;
        q.z = *(unsigned*)&h2; q.w = *(unsigned*)&h3;
        row[v * 32 + lane] = q;
    }
    #pragma unroll
    for (int o = 16; o; o >>= 1) s += __shfl_xor_sync(0xffffffffu, s, o);
    if (lane == 0) g_linv[r] = 1.f / s;
}

// ---------------- K3: pipelined mma.sync GEMM2 (zq = P@book, hi only, k=64) ----------------
// stage: A 18432B + B 18432B; 3 stages
#define G2_STAGE 36864
#define G2_SMEM  (3 * G2_STAGE)

__global__ void __launch_bounds__(256, 2) k_gemm2(float* __restrict__ out) {
    extern __shared__ __align__(1024) char smem[];
    const unsigned sb = sptr(smem);
    const int t = threadIdx.x, lane = t & 31, warp = t >> 5;
    const int rowBase = blockIdx.y * 128, dimBase = blockIdx.x * 128;
    const int wr = warp >> 1, wc = warp & 1;

    float acc[2][8][4];
    #pragma unroll
    for (int i = 0; i < 2; i++)
        #pragma unroll
        for (int j = 0; j < 8; j++)
            #pragma unroll
            for (int c = 0; c < 4; c++) acc[i][j][c] = 0.f;

    auto fill = [&](int c, int s) {
        const int kc = c * 64;
        unsigned ab = sb + s * G2_STAGE;
        unsigned bb = ab + 18432;
        #pragma unroll
        for (int i = 0; i < 4; i++) {
            int id = t + 256 * i;
            int r = id >> 3, cc = id & 7;
            cpa16(ab + r * 144 + cc * 16, &g_Ph [(size_t)(rowBase + r) * BOOK + kc + cc * 8]);
            cpa16(bb + r * 144 + cc * 16, &g_bth[(size_t)(dimBase + r) * BOOK + kc + cc * 8]);
        }
        CP_COMMIT();
    };

    fill(0, 0); fill(1, 1); fill(2, 2);

    for (int it = 0; it < 32; it++) {
        const int s = it % 3;
        CP_WAIT(2);
        __syncthreads();
        const unsigned aB = sb + s * G2_STAGE;
        const unsigned bB = aB + 18432;
        #pragma unroll
        for (int sub = 0; sub < 4; sub++) {
            const int kb = sub * 16;
            unsigned a[2][4], b[4][4];
            #pragma unroll
            for (int i = 0; i < 2; i++)
                ldsm4(aB + ((wr * 32 + i * 16 + (lane & 15)) * 72 + kb + (lane >> 4) * 8) * 2,
                      a[i][0], a[i][1], a[i][2], a[i][3]);
            #pragma unroll
            for (int jj = 0; jj < 4; jj++)
                ldsm4(bB + ((wc * 64 + jj * 16 + (lane & 7) + (lane >> 4) * 8) * 72
                            + kb + ((lane >> 3) & 1) * 8) * 2,
                      b[jj][0], b[jj][1], b[jj][2], b[jj][3]);
            #pragma unroll
            for (int i = 0; i < 2; i++)
                #pragma unroll
                for (int j = 0; j < 8; j++)
                    mma16816(acc[i][j], a[i], b[j >> 1][(j & 1) * 2], b[j >> 1][(j & 1) * 2 + 1]);
        }
        __syncthreads();
        if (it + 3 < 32) fill(it + 3, s); else CP_COMMIT();
    }

    // epilogue: zq = acc * (1/L), float2 stores (even offsets; out base aligned)
    #pragma unroll
    for (int i = 0; i < 2; i++) {
        #pragma unroll
        for (int h = 0; h < 2; h++) {
            const int rl = wr * 32 + i * 16 + (lane >> 2) + h * 8;
            const int grow = rowBase + rl;
            const float linv = g_linv[grow];
            float* __restrict__ orow = out + (size_t)grow * NDIM + dimBase;
            #pragma unroll
            for (int j = 0; j < 8; j++) {
                const int cl = wc * 64 + j * 8 + (lane & 3) * 2;
                *(float2*)&orow[cl] = make_float2(acc[i][j][2 * h] * linv,
                                                  acc[i][j][2 * h + 1] * linv);
            }
        }
    }
}

// ---------------- launcher ----------------
extern "C" void kernel_launch(void* const* d_in, const int* in_sizes, int n_in,
                              void* d_out, int out_size) {
    const float* ze   = (const float*)d_in[0];
    const float* temp = (const float*)d_in[1];
    const float* U    = (const float*)d_in[2];
    const float* book = (const float*)d_in[3];
    const float* lpq  = (const float*)d_in[4];
    float* out = (float*)d_out;

    static int attr_done = 0;
    if (!attr_done) {
        cudaFuncSetAttribute(k_gemm1, cudaFuncAttributeMaxDynamicSharedMemorySize, G1_SMEM);
        cudaFuncSetAttribute(k_gemm2, cudaFuncAttributeMaxDynamicSharedMemorySize, G2_SMEM);
        attr_done = 1;
    }

    k_prep_book<<<BOOK,   NDIM>>>(book);
    k_prep_ze  <<<N_ROWS, NDIM>>>(ze);
    k_scalar<<<1, 1>>>(lpq, out);
    k_gemm1<<<dim3(CBLK, N_ROWS / 128), 256, G1_SMEM>>>(U, temp, lpq, out);
    k_reduce<<<(N_ROWS * 32 + 255) / 256, 256>>>();
    k_gemm2<<<dim3(NDIM / 128, N_ROWS / 128), 256, G2_SMEM>>>(out);
}